// round 12
// baseline (speedup 1.0000x reference)
#include <cuda_runtime.h>
#include <cuda_bf16.h>
#include <math.h>

#define BATCH 32
#define NGT 20
#define HWA 10647
#define NUM_CLASSES 80
#define FP16_EPS_F 0.0009765625
#define BCE_EPS 1e-6f

#define TOTAL (BATCH * HWA)     // 340704
#define TOTAL4 (TOTAL / 4)      // 85176 exact
#define THREADS 256
#define MAIN_BLOCKS 333         // 333*256 = 85248 >= TOTAL4, 1 float4/thread
#define GRID_BLOCKS (MAIN_BLOCKS + BATCH)  // 365

// persistent device state (plain-stored every call; no zeroing needed)
// g_batch[b]: [0]=pb (cls+txty+twth)/npos_clamped  [1]=npos [2]=conf_pos
//             [3]=negsub [4]=touched
__device__ float g_part_sum[MAIN_BLOCKS];
__device__ float g_batch[BATCH][5];
__device__ unsigned int g_done;  // zero-init; self-reset by final block

__constant__ float c_anc[9][2] = {
    {0.024f, 0.031f}, {0.038f, 0.072f}, {0.079f, 0.055f},
    {0.072f, 0.147f}, {0.149f, 0.108f}, {0.142f, 0.286f},
    {0.279f, 0.216f}, {0.375f, 0.476f}, {0.897f, 0.784f}};

__device__ __forceinline__ int grid_of(int j) { return (j == 0) ? 52 : ((j == 1) ? 26 : 13); }
__device__ __forceinline__ int off_of(int j)  { return (j == 0) ? 0  : ((j == 1) ? 2704 : 3380); }

// fast sigmoid: EX2 + RCP. Used identically for main sum and touched-row
// subtraction so the correction cancels to ~1ulp.
__device__ __forceinline__ float sigf(float x) {
    return __fdividef(1.0f, 1.0f + __expf(-x));
}
__device__ __forceinline__ float bcef(float p, float g) {
    p = fminf(fmaxf(p, BCE_EPS), 1.0f - BCE_EPS);
    return -(g * __logf(p) + (1.0f - g) * __logf(1.0f - p));
}

__device__ __forceinline__ float warp_sum_f(float v) {
    #pragma unroll
    for (int s = 16; s > 0; s >>= 1) v += __shfl_xor_sync(0xFFFFFFFFu, v, s);
    return v;
}

__global__ void __launch_bounds__(THREADS)
yolo_loss_kernel(const float* __restrict__ pconf,
                 const float* __restrict__ pcls,
                 const float* __restrict__ ptxywh,
                 const float* __restrict__ gb,
                 const int* __restrict__ glab,
                 float* __restrict__ out) {
    __shared__ float sh_red[THREADS / 32];
    int blk = blockIdx.x;
    int tid = threadIdx.x;
    int lane = tid & 31, warp = tid >> 5;

    if (blk >= BATCH) {
        // ---- main: sum sigmoid(pconf)^2 over all rows, 1 float4/thread ----
        int mb = blk - BATCH;
        int idx = mb * THREADS + tid;
        float acc = 0.0f;
        if (idx < TOTAL4) {
            float4 v = ((const float4*)pconf)[idx];
            float s0 = sigf(v.x), s1 = sigf(v.y), s2 = sigf(v.z), s3 = sigf(v.w);
            acc = s0 * s0 + s1 * s1 + s2 * s2 + s3 * s3;
        }
        acc = warp_sum_f(acc);
        if (lane == 0) sh_red[warp] = acc;
        __syncthreads();
        if (tid == 0) {
            float t = 0.0f;
            #pragma unroll
            for (int w = 0; w < THREADS / 32; w++) t += sh_red[w];
            g_part_sum[mb] = t;
        }
    } else {
        // ---- correction: one block per batch item (closed-form winners) ----
        int b = blk;
        __shared__ float scx[NGT], scy[NGT], swd[NGT], shd[NGT];
        __shared__ int scell[NGT][3];
        __shared__ int sglab[NGT];
        __shared__ int s_a19;
        __shared__ float s_out[2][6];   // v1..v6 partials from warps 0,1
        __shared__ float s_cls;

        if (tid == 0) s_cls = 0.0f;
        if (tid < NGT) {
            const float* p = gb + (b * NGT + tid) * 4;
            float l = p[0], tp = p[1], r = p[2], bo = p[3];
            sglab[tid] = glab[b * NGT + tid];
            float cx = (l + r) * 0.5f, cy = (tp + bo) * 0.5f;
            float w = r - l, h = bo - tp;
            scx[tid] = cx; scy[tid] = cy; swd[tid] = w; shd[tid] = h;
            #pragma unroll
            for (int j = 0; j < 3; j++) {
                int grid = grid_of(j), off = off_of(j);
                int col = (int)(cx * (float)grid);
                int row = (int)(cy * (float)grid);
                scell[tid][j] = (off + row * grid + col) * 3;
            }
            if (tid == NGT - 1) {
                // anchor argmax for GT #19 (only k whose positive events survive)
                float area = w * h;
                float best = -1.0f; int bi = 0;
                #pragma unroll
                for (int a = 0; a < 9; a++) {
                    float aw = c_anc[a][0], ah = c_anc[a][1];
                    float inter = fminf(w, aw) * fminf(h, ah);
                    float uni = area + aw * ah - inter;
                    float iou = inter / uni;
                    if (iou > best) { best = iou; bi = a; }  // first-max like argmax
                }
                s_a19 = bi;
            }
        }
        __syncthreads();

        int a19 = s_a19;
        int js = a19 / 3, ss = a19 % 3;

        // ---- phase B: per-candidate conf/txty/twth (tid < 60) ----
        float v1 = 0.f, v2 = 0.f, v3 = 0.f, v4 = 0.f, v5 = 0.f, v6 = 0.f;
        // v: txty, twth, npos, conf_pos, negsub, touched
        if (tid < NGT * 3) {
            int i = tid / 3;
            int j = tid % 3;
            int C = scell[i][j];
            bool owner = true;   // owner = max-i sharing this (cell, scale)
            for (int i2 = i + 1; i2 < NGT; i2++)
                if (scell[i2][j] == C) { owner = false; break; }

            if (owner) {
                int t0 = b * HWA + C;
                float sc0 = sigf(pconf[t0]);
                float sc1 = sigf(pconf[t0 + 1]);
                float sc2 = sigf(pconf[t0 + 2]);
                v5 = sc0 * sc0 + sc1 * sc1 + sc2 * sc2;
                v6 = 3.0f;

                if (j == js) {
                    int t = t0 + ss;
                    float sc = (ss == 0) ? sc0 : ((ss == 1) ? sc1 : sc2);
                    float d = sc - 1.0f;
                    v4 = d * d;
                    v3 = 1.0f;

                    float cx = scx[i], cy = scy[i], w = swd[i], h = shd[i];
                    float gridf = (float)grid_of(j);
                    int col = (int)(cx * gridf);
                    int rowg = (int)(cy * gridf);
                    float tx = (cx - (float)col / gridf) * gridf;
                    float ty = (cy - (float)rowg / gridf) * gridf;
                    float twx = __logf(w / c_anc[a19][0]);
                    float twy = __logf(h / c_anc[a19][1]);
                    float wt = 2.0f - w * h;

                    const float* pt = ptxywh + (size_t)t * 4;
                    float p0 = sigf(pt[0]);
                    float p1 = sigf(pt[1]);
                    v1 = (bcef(p0, tx) + bcef(p1, ty)) * wt;
                    float d2 = pt[2] - twx, d3 = pt[3] - twy;
                    v2 = (d2 * d2 + d3 * d3) * wt;
                }
            }
        }

        // ---- phase C: 80-class BCE for positive rows, all 8 warps, smem-only
        //      gating (no dependence on phase B's loads -> overlapped gathers)
        for (int i = warp; i < NGT; i += THREADS / 32) {
            int C = scell[i][js];
            bool owner = true;
            for (int i2 = i + 1; i2 < NGT; i2++)
                if (scell[i2][js] == C) { owner = false; break; }
            if (!owner) continue;

            int t = b * HWA + C + ss;
            int lbl = sglab[i] - 1;
            const float* pcp = pcls + (size_t)t * NUM_CLASSES;
            float cls = 0.0f;
            #pragma unroll
            for (int c0 = 0; c0 < NUM_CLASSES; c0 += 32) {
                int c = c0 + lane;
                if (c < NUM_CLASSES) {
                    float p_ = sigf(pcp[c]);
                    p_ = fminf(fmaxf(p_, BCE_EPS), 1.0f - BCE_EPS);
                    cls += (c == lbl) ? -__logf(p_) : -__logf(1.0f - p_);
                }
            }
            cls = warp_sum_f(cls);
            if (lane == 0) atomicAdd(&s_cls, cls);
        }

        // reduce v1..v6 on warps 0,1 (only tid<60 carry data)
        if (warp < 2) {
            v1 = warp_sum_f(v1); v2 = warp_sum_f(v2); v3 = warp_sum_f(v3);
            v4 = warp_sum_f(v4); v5 = warp_sum_f(v5); v6 = warp_sum_f(v6);
            if (lane == 0) {
                s_out[warp][0] = v1; s_out[warp][1] = v2; s_out[warp][2] = v3;
                s_out[warp][3] = v4; s_out[warp][4] = v5; s_out[warp][5] = v6;
            }
        }
        __syncthreads();
        if (tid == 0) {
            float txty = s_out[0][0] + s_out[1][0];
            float twth = s_out[0][1] + s_out[1][1];
            float np   = s_out[0][2] + s_out[1][2];
            float cpos = s_out[0][3] + s_out[1][3];
            float nsub = s_out[0][4] + s_out[1][4];
            float tch  = s_out[0][5] + s_out[1][5];
            float npc = (np < FP16_EPS_F) ? FP16_EPS_F : np;
            g_batch[b][0] = (s_cls + txty + twth) / npc;  // pre-folded pb
            g_batch[b][1] = np;
            g_batch[b][2] = cpos;
            g_batch[b][3] = nsub;
            g_batch[b][4] = tch;
        }
    }

    // ---- last-block-done: final combine ----
    __shared__ unsigned int s_is_last;
    if (tid == 0) {
        __threadfence();
        unsigned int prev = atomicAdd(&g_done, 1u);
        s_is_last = (prev == (unsigned int)(GRID_BLOCKS - 1)) ? 1u : 0u;
    }
    __syncthreads();
    if (!s_is_last) return;
    if (tid == 0) __threadfence();
    __syncthreads();

    // sum main partials (333 floats, one batched round trip)
    float part = 0.0f;
    for (int i = tid; i < MAIN_BLOCKS; i += THREADS) part += g_part_sum[i];
    part = warp_sum_f(part);
    if (lane == 0) sh_red[warp] = part;
    __syncthreads();
    __shared__ float sh_all;
    if (tid == 0) {
        float t = 0.0f;
        #pragma unroll
        for (int w = 0; w < THREADS / 32; w++) t += sh_red[w];
        sh_all = t;
    }

    float pb = 0.0f, npos = 0.0f, cpos = 0.0f, negsub = 0.0f, touched = 0.0f;
    if (tid < BATCH) {
        int b = tid;
        pb      = g_batch[b][0];
        npos    = g_batch[b][1];
        cpos    = g_batch[b][2];
        negsub  = g_batch[b][3];
        touched = g_batch[b][4];
    }
    if (tid < 32) {
        pb = warp_sum_f(pb);
        npos = warp_sum_f(npos);
        cpos = warp_sum_f(cpos);
        negsub = warp_sum_f(negsub);
        touched = warp_sum_f(touched);
    }
    __syncthreads();
    if (tid == 0) {
        double conf_neg_sum = (double)sh_all - (double)negsub;
        double neg_count = (double)TOTAL - (double)touched;
        double l_conf_pos = (double)cpos / (double)npos * 30.0;
        double l_conf_neg = conf_neg_sum / neg_count * 30.0;
        out[0] = (float)(l_conf_pos + l_conf_neg + (double)pb / (double)BATCH);
        g_done = 0u;  // self-reset for next graph replay
    }
}

extern "C" void kernel_launch(void* const* d_in, const int* in_sizes, int n_in,
                              void* d_out, int out_size) {
    const float* pconf  = (const float*)d_in[0];
    const float* pcls   = (const float*)d_in[1];
    const float* ptxywh = (const float*)d_in[2];
    const float* gb     = (const float*)d_in[3];
    const int*   glab   = (const int*)d_in[4];
    float* out = (float*)d_out;

    yolo_loss_kernel<<<GRID_BLOCKS, THREADS>>>(pconf, pcls, ptxywh, gb, glab, out);
}

// round 13
// speedup vs baseline: 1.0021x; 1.0021x over previous
#include <cuda_runtime.h>
#include <cuda_bf16.h>
#include <math.h>

#define BATCH 32
#define NGT 20
#define HWA 10647
#define NUM_CLASSES 80
#define FP16_EPS_F 0.0009765625
#define BCE_EPS 1e-6f

#define TOTAL (BATCH * HWA)     // 340704
#define TOTAL2 (TOTAL / 2)      // 170352 exact
#define THREADS 256
#define MAIN_BLOCKS 666         // 666*256 = 170496 >= TOTAL2, 1 float2/thread
#define GRID_BLOCKS (MAIN_BLOCKS + BATCH)  // 698

// persistent device state (plain-stored every call; no zeroing needed)
// g_batch[b]: [0]=pb (cls+txty+twth)/npos_clamped  [1]=npos [2]=conf_pos
//             [3]=negsub [4]=touched
__device__ float g_part_sum[MAIN_BLOCKS];
__device__ float g_batch[BATCH][5];
__device__ unsigned int g_done;  // zero-init; self-reset by final block

__constant__ float c_anc[9][2] = {
    {0.024f, 0.031f}, {0.038f, 0.072f}, {0.079f, 0.055f},
    {0.072f, 0.147f}, {0.149f, 0.108f}, {0.142f, 0.286f},
    {0.279f, 0.216f}, {0.375f, 0.476f}, {0.897f, 0.784f}};

__device__ __forceinline__ int grid_of(int j) { return (j == 0) ? 52 : ((j == 1) ? 26 : 13); }
__device__ __forceinline__ int off_of(int j)  { return (j == 0) ? 0  : ((j == 1) ? 2704 : 3380); }

// fast sigmoid: EX2 + RCP. Used identically for main sum and touched-row
// subtraction so the correction cancels to ~1ulp.
__device__ __forceinline__ float sigf(float x) {
    return __fdividef(1.0f, 1.0f + __expf(-x));
}
__device__ __forceinline__ float bcef(float p, float g) {
    p = fminf(fmaxf(p, BCE_EPS), 1.0f - BCE_EPS);
    return -(g * __logf(p) + (1.0f - g) * __logf(1.0f - p));
}

__device__ __forceinline__ float warp_sum_f(float v) {
    #pragma unroll
    for (int s = 16; s > 0; s >>= 1) v += __shfl_xor_sync(0xFFFFFFFFu, v, s);
    return v;
}

__global__ void __launch_bounds__(THREADS)
yolo_loss_kernel(const float* __restrict__ pconf,
                 const float* __restrict__ pcls,
                 const float* __restrict__ ptxywh,
                 const float* __restrict__ gb,
                 const int* __restrict__ glab,
                 float* __restrict__ out) {
    __shared__ float sh_red[THREADS / 32];
    int blk = blockIdx.x;
    int tid = threadIdx.x;
    int lane = tid & 31, warp = tid >> 5;

    if (blk >= BATCH) {
        // ---- main: sum sigmoid(pconf)^2 over all rows, 1 float2/thread ----
        int mb = blk - BATCH;
        int idx = mb * THREADS + tid;
        float acc = 0.0f;
        if (idx < TOTAL2) {
            float2 v = ((const float2*)pconf)[idx];
            float s0 = sigf(v.x), s1 = sigf(v.y);
            acc = s0 * s0 + s1 * s1;
        }
        acc = warp_sum_f(acc);
        if (lane == 0) sh_red[warp] = acc;
        __syncthreads();
        if (tid == 0) {
            float t = 0.0f;
            #pragma unroll
            for (int w = 0; w < THREADS / 32; w++) t += sh_red[w];
            g_part_sum[mb] = t;
        }
    } else {
        // ---- correction: one block per batch item (closed-form winners) ----
        int b = blk;
        __shared__ float scx[NGT], scy[NGT], swd[NGT], shd[NGT];
        __shared__ int scell[NGT][3];
        __shared__ int sglab[NGT];
        __shared__ int s_a19;
        __shared__ float s_out[2][6];   // v1..v6 partials from warps 0,1
        __shared__ float s_cls;

        if (tid == 0) s_cls = 0.0f;
        if (tid < NGT) {
            const float* p = gb + (b * NGT + tid) * 4;
            float l = p[0], tp = p[1], r = p[2], bo = p[3];
            sglab[tid] = glab[b * NGT + tid];
            float cx = (l + r) * 0.5f, cy = (tp + bo) * 0.5f;
            float w = r - l, h = bo - tp;
            scx[tid] = cx; scy[tid] = cy; swd[tid] = w; shd[tid] = h;
            #pragma unroll
            for (int j = 0; j < 3; j++) {
                int grid = grid_of(j), off = off_of(j);
                int col = (int)(cx * (float)grid);
                int row = (int)(cy * (float)grid);
                scell[tid][j] = (off + row * grid + col) * 3;
            }
            if (tid == NGT - 1) {
                // anchor argmax for GT #19 (only k whose positive events survive)
                float area = w * h;
                float best = -1.0f; int bi = 0;
                #pragma unroll
                for (int a = 0; a < 9; a++) {
                    float aw = c_anc[a][0], ah = c_anc[a][1];
                    float inter = fminf(w, aw) * fminf(h, ah);
                    float uni = area + aw * ah - inter;
                    float iou = inter / uni;
                    if (iou > best) { best = iou; bi = a; }  // first-max like argmax
                }
                s_a19 = bi;
            }
        }
        __syncthreads();

        int a19 = s_a19;
        int js = a19 / 3, ss = a19 % 3;

        // ---- phase B: per-candidate conf/txty/twth (tid < 60) ----
        float v1 = 0.f, v2 = 0.f, v3 = 0.f, v4 = 0.f, v5 = 0.f, v6 = 0.f;
        // v: txty, twth, npos, conf_pos, negsub, touched
        if (tid < NGT * 3) {
            int i = tid / 3;
            int j = tid % 3;
            int C = scell[i][j];
            bool owner = true;   // owner = max-i sharing this (cell, scale)
            for (int i2 = i + 1; i2 < NGT; i2++)
                if (scell[i2][j] == C) { owner = false; break; }

            if (owner) {
                int t0 = b * HWA + C;
                float sc0 = sigf(pconf[t0]);
                float sc1 = sigf(pconf[t0 + 1]);
                float sc2 = sigf(pconf[t0 + 2]);
                v5 = sc0 * sc0 + sc1 * sc1 + sc2 * sc2;
                v6 = 3.0f;

                if (j == js) {
                    int t = t0 + ss;
                    float sc = (ss == 0) ? sc0 : ((ss == 1) ? sc1 : sc2);
                    float d = sc - 1.0f;
                    v4 = d * d;
                    v3 = 1.0f;

                    float cx = scx[i], cy = scy[i], w = swd[i], h = shd[i];
                    float gridf = (float)grid_of(j);
                    int col = (int)(cx * gridf);
                    int rowg = (int)(cy * gridf);
                    float tx = (cx - (float)col / gridf) * gridf;
                    float ty = (cy - (float)rowg / gridf) * gridf;
                    float twx = __logf(w / c_anc[a19][0]);
                    float twy = __logf(h / c_anc[a19][1]);
                    float wt = 2.0f - w * h;

                    const float* pt = ptxywh + (size_t)t * 4;
                    float p0 = sigf(pt[0]);
                    float p1 = sigf(pt[1]);
                    v1 = (bcef(p0, tx) + bcef(p1, ty)) * wt;
                    float d2 = pt[2] - twx, d3 = pt[3] - twy;
                    v2 = (d2 * d2 + d3 * d3) * wt;
                }
            }
        }

        // ---- phase C: 80-class BCE for positive rows, all 8 warps, smem-only
        //      gating (no dependence on phase B's loads -> overlapped gathers)
        for (int i = warp; i < NGT; i += THREADS / 32) {
            int C = scell[i][js];
            bool owner = true;
            for (int i2 = i + 1; i2 < NGT; i2++)
                if (scell[i2][js] == C) { owner = false; break; }
            if (!owner) continue;

            int t = b * HWA + C + ss;
            int lbl = sglab[i] - 1;
            const float* pcp = pcls + (size_t)t * NUM_CLASSES;
            float cls = 0.0f;
            #pragma unroll
            for (int c0 = 0; c0 < NUM_CLASSES; c0 += 32) {
                int c = c0 + lane;
                if (c < NUM_CLASSES) {
                    float p_ = sigf(pcp[c]);
                    p_ = fminf(fmaxf(p_, BCE_EPS), 1.0f - BCE_EPS);
                    cls += (c == lbl) ? -__logf(p_) : -__logf(1.0f - p_);
                }
            }
            cls = warp_sum_f(cls);
            if (lane == 0) atomicAdd(&s_cls, cls);
        }

        // reduce v1..v6 on warps 0,1 (only tid<60 carry data)
        if (warp < 2) {
            v1 = warp_sum_f(v1); v2 = warp_sum_f(v2); v3 = warp_sum_f(v3);
            v4 = warp_sum_f(v4); v5 = warp_sum_f(v5); v6 = warp_sum_f(v6);
            if (lane == 0) {
                s_out[warp][0] = v1; s_out[warp][1] = v2; s_out[warp][2] = v3;
                s_out[warp][3] = v4; s_out[warp][4] = v5; s_out[warp][5] = v6;
            }
        }
        __syncthreads();
        if (tid == 0) {
            float txty = s_out[0][0] + s_out[1][0];
            float twth = s_out[0][1] + s_out[1][1];
            float np   = s_out[0][2] + s_out[1][2];
            float cpos = s_out[0][3] + s_out[1][3];
            float nsub = s_out[0][4] + s_out[1][4];
            float tch  = s_out[0][5] + s_out[1][5];
            float npc = (np < FP16_EPS_F) ? FP16_EPS_F : np;
            g_batch[b][0] = (s_cls + txty + twth) / npc;  // pre-folded pb
            g_batch[b][1] = np;
            g_batch[b][2] = cpos;
            g_batch[b][3] = nsub;
            g_batch[b][4] = tch;
        }
    }

    // ---- last-block-done: final combine ----
    __shared__ unsigned int s_is_last;
    if (tid == 0) {
        __threadfence();
        unsigned int prev = atomicAdd(&g_done, 1u);
        s_is_last = (prev == (unsigned int)(GRID_BLOCKS - 1)) ? 1u : 0u;
    }
    __syncthreads();
    if (!s_is_last) return;
    if (tid == 0) __threadfence();
    __syncthreads();

    // sum main partials (666 floats, batched, one round trip)
    float part = 0.0f;
    for (int i = tid; i < MAIN_BLOCKS; i += THREADS) part += g_part_sum[i];
    part = warp_sum_f(part);
    if (lane == 0) sh_red[warp] = part;
    __syncthreads();
    __shared__ float sh_all;
    if (tid == 0) {
        float t = 0.0f;
        #pragma unroll
        for (int w = 0; w < THREADS / 32; w++) t += sh_red[w];
        sh_all = t;
    }

    float pb = 0.0f, npos = 0.0f, cpos = 0.0f, negsub = 0.0f, touched = 0.0f;
    if (tid < BATCH) {
        int b = tid;
        pb      = g_batch[b][0];
        npos    = g_batch[b][1];
        cpos    = g_batch[b][2];
        negsub  = g_batch[b][3];
        touched = g_batch[b][4];
    }
    if (tid < 32) {
        pb = warp_sum_f(pb);
        npos = warp_sum_f(npos);
        cpos = warp_sum_f(cpos);
        negsub = warp_sum_f(negsub);
        touched = warp_sum_f(touched);
    }
    __syncthreads();
    if (tid == 0) {
        double conf_neg_sum = (double)sh_all - (double)negsub;
        double neg_count = (double)TOTAL - (double)touched;
        double l_conf_pos = (double)cpos / (double)npos * 30.0;
        double l_conf_neg = conf_neg_sum / neg_count * 30.0;
        out[0] = (float)(l_conf_pos + l_conf_neg + (double)pb / (double)BATCH);
        g_done = 0u;  // self-reset for next graph replay
    }
}

extern "C" void kernel_launch(void* const* d_in, const int* in_sizes, int n_in,
                              void* d_out, int out_size) {
    const float* pconf  = (const float*)d_in[0];
    const float* pcls   = (const float*)d_in[1];
    const float* ptxywh = (const float*)d_in[2];
    const float* gb     = (const float*)d_in[3];
    const int*   glab   = (const int*)d_in[4];
    float* out = (float*)d_out;

    yolo_loss_kernel<<<GRID_BLOCKS, THREADS>>>(pconf, pcls, ptxywh, gb, glab, out);
}

// round 14
// speedup vs baseline: 1.1597x; 1.1572x over previous
#include <cuda_runtime.h>
#include <cuda_bf16.h>
#include <math.h>

#define BATCH 32
#define NGT 20
#define HWA 10647
#define NUM_CLASSES 80
#define FP16_EPS_F 0.0009765625
#define BCE_EPS 1e-6f

#define TOTAL (BATCH * HWA)     // 340704
#define TOTAL4 (TOTAL / 4)      // 85176 exact
#define THREADS 256
#define MAIN_BLOCKS 333         // 333*256 = 85248 >= TOTAL4, 1 float4/thread
#define GRID_BLOCKS (MAIN_BLOCKS + BATCH)  // 365

// persistent device state (plain-stored every call; no zeroing needed)
// g_batch[b]: [0]=pb (cls+txty+twth)/npos_clamped  [1]=npos [2]=conf_pos
//             [3]=negsub [4]=touched
__device__ float g_part_sum[MAIN_BLOCKS];
__device__ float g_batch[BATCH][5];
__device__ float g_main_total;      // published by last main block
__device__ unsigned int g_done_main;  // main-block arrivals; self-reset
__device__ unsigned int g_done_all;   // all-block arrivals; self-reset

__constant__ float c_anc[9][2] = {
    {0.024f, 0.031f}, {0.038f, 0.072f}, {0.079f, 0.055f},
    {0.072f, 0.147f}, {0.149f, 0.108f}, {0.142f, 0.286f},
    {0.279f, 0.216f}, {0.375f, 0.476f}, {0.897f, 0.784f}};

__device__ __forceinline__ int grid_of(int j) { return (j == 0) ? 52 : ((j == 1) ? 26 : 13); }
__device__ __forceinline__ int off_of(int j)  { return (j == 0) ? 0  : ((j == 1) ? 2704 : 3380); }

// fast sigmoid: EX2 + RCP. Used identically for main sum and touched-row
// subtraction so the correction cancels to ~1ulp.
__device__ __forceinline__ float sigf(float x) {
    return __fdividef(1.0f, 1.0f + __expf(-x));
}
__device__ __forceinline__ float bcef(float p, float g) {
    p = fminf(fmaxf(p, BCE_EPS), 1.0f - BCE_EPS);
    return -(g * __logf(p) + (1.0f - g) * __logf(1.0f - p));
}

__device__ __forceinline__ float warp_sum_f(float v) {
    #pragma unroll
    for (int s = 16; s > 0; s >>= 1) v += __shfl_xor_sync(0xFFFFFFFFu, v, s);
    return v;
}

__global__ void __launch_bounds__(THREADS)
yolo_loss_kernel(const float* __restrict__ pconf,
                 const float* __restrict__ pcls,
                 const float* __restrict__ ptxywh,
                 const float* __restrict__ gb,
                 const int* __restrict__ glab,
                 float* __restrict__ out) {
    __shared__ float sh_red[THREADS / 32];
    int blk = blockIdx.x;
    int tid = threadIdx.x;
    int lane = tid & 31, warp = tid >> 5;

    if (blk >= BATCH) {
        // ---- main: sum sigmoid(pconf)^2 over all rows, 1 float4/thread ----
        int mb = blk - BATCH;
        int idx = mb * THREADS + tid;
        float acc = 0.0f;
        if (idx < TOTAL4) {
            float4 v = ((const float4*)pconf)[idx];
            float s0 = sigf(v.x), s1 = sigf(v.y), s2 = sigf(v.z), s3 = sigf(v.w);
            acc = s0 * s0 + s1 * s1 + s2 * s2 + s3 * s3;
        }
        acc = warp_sum_f(acc);
        if (lane == 0) sh_red[warp] = acc;
        __syncthreads();
        if (tid == 0) {
            float t = 0.0f;
            #pragma unroll
            for (int w = 0; w < THREADS / 32; w++) t += sh_red[w];
            g_part_sum[mb] = t;
        }

        // ---- stage-A completion: last main block folds the 333 partials ----
        __shared__ unsigned int s_last_main;
        if (tid == 0) {
            __threadfence();
            unsigned int prev = atomicAdd(&g_done_main, 1u);
            s_last_main = (prev == (unsigned int)(MAIN_BLOCKS - 1)) ? 1u : 0u;
        }
        __syncthreads();
        if (s_last_main) {
            if (tid == 0) __threadfence();
            __syncthreads();
            float part = 0.0f;
            for (int i = tid; i < MAIN_BLOCKS; i += THREADS) part += g_part_sum[i];
            part = warp_sum_f(part);
            if (lane == 0) sh_red[warp] = part;
            __syncthreads();
            if (tid == 0) {
                float t = 0.0f;
                #pragma unroll
                for (int w = 0; w < THREADS / 32; w++) t += sh_red[w];
                g_main_total = t;
                g_done_main = 0u;  // self-reset for next graph replay
            }
        }
    } else {
        // ---- correction: one block per batch item (closed-form winners) ----
        int b = blk;
        __shared__ float scx[NGT], scy[NGT], swd[NGT], shd[NGT];
        __shared__ int scell[NGT][3];
        __shared__ int sglab[NGT];
        __shared__ int s_a19;
        __shared__ float s_out[2][6];   // v1..v6 partials from warps 0,1
        __shared__ float s_cls;

        if (tid == 0) s_cls = 0.0f;
        if (tid < NGT) {
            const float* p = gb + (b * NGT + tid) * 4;
            float l = p[0], tp = p[1], r = p[2], bo = p[3];
            sglab[tid] = glab[b * NGT + tid];
            float cx = (l + r) * 0.5f, cy = (tp + bo) * 0.5f;
            float w = r - l, h = bo - tp;
            scx[tid] = cx; scy[tid] = cy; swd[tid] = w; shd[tid] = h;
            #pragma unroll
            for (int j = 0; j < 3; j++) {
                int grid = grid_of(j), off = off_of(j);
                int col = (int)(cx * (float)grid);
                int row = (int)(cy * (float)grid);
                scell[tid][j] = (off + row * grid + col) * 3;
            }
            if (tid == NGT - 1) {
                // anchor argmax for GT #19 (only k whose positive events survive)
                float area = w * h;
                float best = -1.0f; int bi = 0;
                #pragma unroll
                for (int a = 0; a < 9; a++) {
                    float aw = c_anc[a][0], ah = c_anc[a][1];
                    float inter = fminf(w, aw) * fminf(h, ah);
                    float uni = area + aw * ah - inter;
                    float iou = inter / uni;
                    if (iou > best) { best = iou; bi = a; }  // first-max like argmax
                }
                s_a19 = bi;
            }
        }
        __syncthreads();

        int a19 = s_a19;
        int js = a19 / 3, ss = a19 % 3;

        // ---- phase B: per-candidate conf/txty/twth (tid < 60) ----
        float v1 = 0.f, v2 = 0.f, v3 = 0.f, v4 = 0.f, v5 = 0.f, v6 = 0.f;
        // v: txty, twth, npos, conf_pos, negsub, touched
        if (tid < NGT * 3) {
            int i = tid / 3;
            int j = tid % 3;
            int C = scell[i][j];
            bool owner = true;   // owner = max-i sharing this (cell, scale)
            for (int i2 = i + 1; i2 < NGT; i2++)
                if (scell[i2][j] == C) { owner = false; break; }

            if (owner) {
                int t0 = b * HWA + C;
                float sc0 = sigf(pconf[t0]);
                float sc1 = sigf(pconf[t0 + 1]);
                float sc2 = sigf(pconf[t0 + 2]);
                v5 = sc0 * sc0 + sc1 * sc1 + sc2 * sc2;
                v6 = 3.0f;

                if (j == js) {
                    int t = t0 + ss;
                    float sc = (ss == 0) ? sc0 : ((ss == 1) ? sc1 : sc2);
                    float d = sc - 1.0f;
                    v4 = d * d;
                    v3 = 1.0f;

                    float cx = scx[i], cy = scy[i], w = swd[i], h = shd[i];
                    float gridf = (float)grid_of(j);
                    int col = (int)(cx * gridf);
                    int rowg = (int)(cy * gridf);
                    float tx = (cx - (float)col / gridf) * gridf;
                    float ty = (cy - (float)rowg / gridf) * gridf;
                    float twx = __logf(w / c_anc[a19][0]);
                    float twy = __logf(h / c_anc[a19][1]);
                    float wt = 2.0f - w * h;

                    const float* pt = ptxywh + (size_t)t * 4;
                    float p0 = sigf(pt[0]);
                    float p1 = sigf(pt[1]);
                    v1 = (bcef(p0, tx) + bcef(p1, ty)) * wt;
                    float d2 = pt[2] - twx, d3 = pt[3] - twy;
                    v2 = (d2 * d2 + d3 * d3) * wt;
                }
            }
        }

        // ---- phase C: 80-class BCE for positive rows, all 8 warps, smem-only
        //      gating (no dependence on phase B's loads -> overlapped gathers)
        for (int i = warp; i < NGT; i += THREADS / 32) {
            int C = scell[i][js];
            bool owner = true;
            for (int i2 = i + 1; i2 < NGT; i2++)
                if (scell[i2][js] == C) { owner = false; break; }
            if (!owner) continue;

            int t = b * HWA + C + ss;
            int lbl = sglab[i] - 1;
            const float* pcp = pcls + (size_t)t * NUM_CLASSES;
            float cls = 0.0f;
            #pragma unroll
            for (int c0 = 0; c0 < NUM_CLASSES; c0 += 32) {
                int c = c0 + lane;
                if (c < NUM_CLASSES) {
                    float p_ = sigf(pcp[c]);
                    p_ = fminf(fmaxf(p_, BCE_EPS), 1.0f - BCE_EPS);
                    cls += (c == lbl) ? -__logf(p_) : -__logf(1.0f - p_);
                }
            }
            cls = warp_sum_f(cls);
            if (lane == 0) atomicAdd(&s_cls, cls);
        }

        // reduce v1..v6 on warps 0,1 (only tid<60 carry data)
        if (warp < 2) {
            v1 = warp_sum_f(v1); v2 = warp_sum_f(v2); v3 = warp_sum_f(v3);
            v4 = warp_sum_f(v4); v5 = warp_sum_f(v5); v6 = warp_sum_f(v6);
            if (lane == 0) {
                s_out[warp][0] = v1; s_out[warp][1] = v2; s_out[warp][2] = v3;
                s_out[warp][3] = v4; s_out[warp][4] = v5; s_out[warp][5] = v6;
            }
        }
        __syncthreads();
        if (tid == 0) {
            float txty = s_out[0][0] + s_out[1][0];
            float twth = s_out[0][1] + s_out[1][1];
            float np   = s_out[0][2] + s_out[1][2];
            float cpos = s_out[0][3] + s_out[1][3];
            float nsub = s_out[0][4] + s_out[1][4];
            float tch  = s_out[0][5] + s_out[1][5];
            float npc = (np < FP16_EPS_F) ? FP16_EPS_F : np;
            g_batch[b][0] = (s_cls + txty + twth) / npc;  // pre-folded pb
            g_batch[b][1] = np;
            g_batch[b][2] = cpos;
            g_batch[b][3] = nsub;
            g_batch[b][4] = tch;
        }
    }

    // ---- stage-B completion: final combine (single round trip tail) ----
    __shared__ unsigned int s_is_last;
    if (tid == 0) {
        __threadfence();
        unsigned int prev = atomicAdd(&g_done_all, 1u);
        s_is_last = (prev == (unsigned int)(GRID_BLOCKS - 1)) ? 1u : 0u;
    }
    __syncthreads();
    if (!s_is_last) return;
    if (tid == 0) __threadfence();
    __syncthreads();

    // one batched read: g_main_total + 160 batch floats
    float pb = 0.0f, npos = 0.0f, cpos = 0.0f, negsub = 0.0f, touched = 0.0f;
    if (tid < BATCH) {
        int b = tid;
        pb      = g_batch[b][0];
        npos    = g_batch[b][1];
        cpos    = g_batch[b][2];
        negsub  = g_batch[b][3];
        touched = g_batch[b][4];
    }
    __shared__ float sh_all;
    if (tid == 32) sh_all = g_main_total;   // issued in parallel with batch reads
    if (tid < 32) {
        pb = warp_sum_f(pb);
        npos = warp_sum_f(npos);
        cpos = warp_sum_f(cpos);
        negsub = warp_sum_f(negsub);
        touched = warp_sum_f(touched);
    }
    __syncthreads();
    if (tid == 0) {
        double conf_neg_sum = (double)sh_all - (double)negsub;
        double neg_count = (double)TOTAL - (double)touched;
        double l_conf_pos = (double)cpos / (double)npos * 30.0;
        double l_conf_neg = conf_neg_sum / neg_count * 30.0;
        out[0] = (float)(l_conf_pos + l_conf_neg + (double)pb / (double)BATCH);
        g_done_all = 0u;  // self-reset for next graph replay
    }
}

extern "C" void kernel_launch(void* const* d_in, const int* in_sizes, int n_in,
                              void* d_out, int out_size) {
    const float* pconf  = (const float*)d_in[0];
    const float* pcls   = (const float*)d_in[1];
    const float* ptxywh = (const float*)d_in[2];
    const float* gb     = (const float*)d_in[3];
    const int*   glab   = (const int*)d_in[4];
    float* out = (float*)d_out;

    yolo_loss_kernel<<<GRID_BLOCKS, THREADS>>>(pconf, pcls, ptxywh, gb, glab, out);
}

// round 15
// speedup vs baseline: 1.1889x; 1.0252x over previous
#include <cuda_runtime.h>
#include <cuda_bf16.h>
#include <math.h>

#define BATCH 32
#define NGT 20
#define HWA 10647
#define NUM_CLASSES 80
#define FP16_EPS_F 0.0009765625
#define BCE_EPS 1e-6f

#define TOTAL (BATCH * HWA)     // 340704
#define TOTAL4 (TOTAL / 4)      // 85176 exact
#define THREADS 256
#define MAIN_BLOCKS 333         // 333*256 = 85248 >= TOTAL4, 1 float4/thread
#define GRID_BLOCKS (MAIN_BLOCKS + BATCH)  // 365

// persistent device state (plain-stored every call; no zeroing needed)
// g_batch[b]: [0]=pb (cls+txty+twth)/npos_clamped  [1]=npos [2]=conf_pos
//             [3]=negsub [4]=touched
__device__ float g_part_sum[MAIN_BLOCKS];
__device__ float g_batch[BATCH][5];
__device__ float g_main_total;      // published by last main block
__device__ unsigned int g_done_main;  // main-block arrivals; self-reset
__device__ unsigned int g_done_all;   // all-block arrivals; self-reset

__constant__ float c_anc[9][2] = {
    {0.024f, 0.031f}, {0.038f, 0.072f}, {0.079f, 0.055f},
    {0.072f, 0.147f}, {0.149f, 0.108f}, {0.142f, 0.286f},
    {0.279f, 0.216f}, {0.375f, 0.476f}, {0.897f, 0.784f}};

__device__ __forceinline__ int grid_of(int j) { return (j == 0) ? 52 : ((j == 1) ? 26 : 13); }
__device__ __forceinline__ int off_of(int j)  { return (j == 0) ? 0  : ((j == 1) ? 2704 : 3380); }

// fast sigmoid: EX2 + RCP. Used identically for main sum and touched-row
// subtraction so the correction cancels to ~1ulp.
__device__ __forceinline__ float sigf(float x) {
    return __fdividef(1.0f, 1.0f + __expf(-x));
}
__device__ __forceinline__ float bcef(float p, float g) {
    p = fminf(fmaxf(p, BCE_EPS), 1.0f - BCE_EPS);
    return -(g * __logf(p) + (1.0f - g) * __logf(1.0f - p));
}

__device__ __forceinline__ float warp_sum_f(float v) {
    #pragma unroll
    for (int s = 16; s > 0; s >>= 1) v += __shfl_xor_sync(0xFFFFFFFFu, v, s);
    return v;
}

__global__ void __launch_bounds__(THREADS)
yolo_loss_kernel(const float* __restrict__ pconf,
                 const float* __restrict__ pcls,
                 const float* __restrict__ ptxywh,
                 const float* __restrict__ gb,
                 const int* __restrict__ glab,
                 float* __restrict__ out) {
    __shared__ float sh_red[THREADS / 32];
    int blk = blockIdx.x;
    int tid = threadIdx.x;
    int lane = tid & 31, warp = tid >> 5;

    if (blk >= BATCH) {
        // ---- main: sum sigmoid(pconf)^2 over all rows, 1 float4/thread ----
        int mb = blk - BATCH;
        int idx = mb * THREADS + tid;
        float acc = 0.0f;
        if (idx < TOTAL4) {
            float4 v = ((const float4*)pconf)[idx];
            float s0 = sigf(v.x), s1 = sigf(v.y), s2 = sigf(v.z), s3 = sigf(v.w);
            acc = s0 * s0 + s1 * s1 + s2 * s2 + s3 * s3;
        }
        acc = warp_sum_f(acc);
        if (lane == 0) sh_red[warp] = acc;
        __syncthreads();
        if (tid == 0) {
            float t = 0.0f;
            #pragma unroll
            for (int w = 0; w < THREADS / 32; w++) t += sh_red[w];
            g_part_sum[mb] = t;
        }

        // ---- stage-A completion: last main block folds the 333 partials ----
        __shared__ unsigned int s_last_main;
        if (tid == 0) {
            __threadfence();
            unsigned int prev = atomicAdd(&g_done_main, 1u);
            s_last_main = (prev == (unsigned int)(MAIN_BLOCKS - 1)) ? 1u : 0u;
        }
        __syncthreads();
        if (s_last_main) {
            if (tid == 0) __threadfence();
            __syncthreads();
            float part = 0.0f;
            for (int i = tid; i < MAIN_BLOCKS; i += THREADS) part += g_part_sum[i];
            part = warp_sum_f(part);
            if (lane == 0) sh_red[warp] = part;
            __syncthreads();
            if (tid == 0) {
                float t = 0.0f;
                #pragma unroll
                for (int w = 0; w < THREADS / 32; w++) t += sh_red[w];
                g_main_total = t;
                g_done_main = 0u;  // self-reset for next graph replay
            }
        }
    } else {
        // ---- correction: one block per batch item (closed-form winners) ----
        int b = blk;
        __shared__ float scx[NGT], scy[NGT], swd[NGT], shd[NGT];
        __shared__ int scell[NGT][3];
        __shared__ int sglab[NGT];
        __shared__ int s_a19;
        __shared__ float s_out[2][6];   // v1..v6 partials from warps 0,1
        __shared__ float s_cls;

        if (tid == 0) s_cls = 0.0f;
        if (tid < NGT) {
            const float* p = gb + (b * NGT + tid) * 4;
            float l = p[0], tp = p[1], r = p[2], bo = p[3];
            sglab[tid] = glab[b * NGT + tid];
            float cx = (l + r) * 0.5f, cy = (tp + bo) * 0.5f;
            float w = r - l, h = bo - tp;
            scx[tid] = cx; scy[tid] = cy; swd[tid] = w; shd[tid] = h;
            #pragma unroll
            for (int j = 0; j < 3; j++) {
                int grid = grid_of(j), off = off_of(j);
                int col = (int)(cx * (float)grid);
                int row = (int)(cy * (float)grid);
                scell[tid][j] = (off + row * grid + col) * 3;
            }
            if (tid == NGT - 1) {
                // anchor argmax for GT #19 (only k whose positive events survive)
                float area = w * h;
                float best = -1.0f; int bi = 0;
                #pragma unroll
                for (int a = 0; a < 9; a++) {
                    float aw = c_anc[a][0], ah = c_anc[a][1];
                    float inter = fminf(w, aw) * fminf(h, ah);
                    float uni = area + aw * ah - inter;
                    float iou = inter / uni;
                    if (iou > best) { best = iou; bi = a; }  // first-max like argmax
                }
                s_a19 = bi;
            }
        }
        __syncthreads();

        int a19 = s_a19;
        int js = a19 / 3, ss = a19 % 3;

        // ---- phase B: per-candidate conf/txty/twth (tid < 60) ----
        float v1 = 0.f, v2 = 0.f, v3 = 0.f, v4 = 0.f, v5 = 0.f, v6 = 0.f;
        // v: txty, twth, npos, conf_pos, negsub, touched
        if (tid < NGT * 3) {
            int i = tid / 3;
            int j = tid % 3;
            int C = scell[i][j];
            bool owner = true;   // owner = max-i sharing this (cell, scale)
            for (int i2 = i + 1; i2 < NGT; i2++)
                if (scell[i2][j] == C) { owner = false; break; }

            if (owner) {
                int t0 = b * HWA + C;
                float sc0 = sigf(pconf[t0]);
                float sc1 = sigf(pconf[t0 + 1]);
                float sc2 = sigf(pconf[t0 + 2]);
                v5 = sc0 * sc0 + sc1 * sc1 + sc2 * sc2;
                v6 = 3.0f;

                if (j == js) {
                    int t = t0 + ss;
                    float sc = (ss == 0) ? sc0 : ((ss == 1) ? sc1 : sc2);
                    float d = sc - 1.0f;
                    v4 = d * d;
                    v3 = 1.0f;

                    float cx = scx[i], cy = scy[i], w = swd[i], h = shd[i];
                    float gridf = (float)grid_of(j);
                    int col = (int)(cx * gridf);
                    int rowg = (int)(cy * gridf);
                    float tx = (cx - (float)col / gridf) * gridf;
                    float ty = (cy - (float)rowg / gridf) * gridf;
                    float twx = __logf(w / c_anc[a19][0]);
                    float twy = __logf(h / c_anc[a19][1]);
                    float wt = 2.0f - w * h;

                    const float* pt = ptxywh + (size_t)t * 4;
                    float p0 = sigf(pt[0]);
                    float p1 = sigf(pt[1]);
                    v1 = (bcef(p0, tx) + bcef(p1, ty)) * wt;
                    float d2 = pt[2] - twx, d3 = pt[3] - twy;
                    v2 = (d2 * d2 + d3 * d3) * wt;
                }
            }
        }

        // ---- phase C: 80-class BCE for positive rows, all 8 warps, smem-only
        //      gating (no dependence on phase B's loads -> overlapped gathers)
        for (int i = warp; i < NGT; i += THREADS / 32) {
            int C = scell[i][js];
            bool owner = true;
            for (int i2 = i + 1; i2 < NGT; i2++)
                if (scell[i2][js] == C) { owner = false; break; }
            if (!owner) continue;

            int t = b * HWA + C + ss;
            int lbl = sglab[i] - 1;
            const float* pcp = pcls + (size_t)t * NUM_CLASSES;
            float cls = 0.0f;
            #pragma unroll
            for (int c0 = 0; c0 < NUM_CLASSES; c0 += 32) {
                int c = c0 + lane;
                if (c < NUM_CLASSES) {
                    float p_ = sigf(pcp[c]);
                    p_ = fminf(fmaxf(p_, BCE_EPS), 1.0f - BCE_EPS);
                    cls += (c == lbl) ? -__logf(p_) : -__logf(1.0f - p_);
                }
            }
            cls = warp_sum_f(cls);
            if (lane == 0) atomicAdd(&s_cls, cls);
        }

        // reduce v1..v6 on warps 0,1 (only tid<60 carry data)
        if (warp < 2) {
            v1 = warp_sum_f(v1); v2 = warp_sum_f(v2); v3 = warp_sum_f(v3);
            v4 = warp_sum_f(v4); v5 = warp_sum_f(v5); v6 = warp_sum_f(v6);
            if (lane == 0) {
                s_out[warp][0] = v1; s_out[warp][1] = v2; s_out[warp][2] = v3;
                s_out[warp][3] = v4; s_out[warp][4] = v5; s_out[warp][5] = v6;
            }
        }
        __syncthreads();
        if (tid == 0) {
            float txty = s_out[0][0] + s_out[1][0];
            float twth = s_out[0][1] + s_out[1][1];
            float np   = s_out[0][2] + s_out[1][2];
            float cpos = s_out[0][3] + s_out[1][3];
            float nsub = s_out[0][4] + s_out[1][4];
            float tch  = s_out[0][5] + s_out[1][5];
            float npc = (np < FP16_EPS_F) ? FP16_EPS_F : np;
            g_batch[b][0] = (s_cls + txty + twth) / npc;  // pre-folded pb
            g_batch[b][1] = np;
            g_batch[b][2] = cpos;
            g_batch[b][3] = nsub;
            g_batch[b][4] = tch;
        }
    }

    // ---- stage-B completion: final combine (single round trip tail) ----
    __shared__ unsigned int s_is_last;
    if (tid == 0) {
        __threadfence();
        unsigned int prev = atomicAdd(&g_done_all, 1u);
        s_is_last = (prev == (unsigned int)(GRID_BLOCKS - 1)) ? 1u : 0u;
    }
    __syncthreads();
    if (!s_is_last) return;
    if (tid == 0) __threadfence();
    __syncthreads();

    // one quantity per warp: warp w reduces g_batch[:][w]; warp 5 gets total.
    __shared__ float sh_q[5];
    __shared__ float sh_all;
    if (warp < 5) {
        float v = g_batch[lane][warp];
        v = warp_sum_f(v);
        if (lane == 0) sh_q[warp] = v;
    } else if (warp == 5 && lane == 0) {
        sh_all = g_main_total;
    }
    __syncthreads();
    if (tid == 0) {
        float pb = sh_q[0], npos = sh_q[1], cpos = sh_q[2];
        float negsub = sh_q[3], touched = sh_q[4];
        double conf_neg_sum = (double)sh_all - (double)negsub;
        double neg_count = (double)TOTAL - (double)touched;
        double l_conf_pos = (double)cpos / (double)npos * 30.0;
        double l_conf_neg = conf_neg_sum / neg_count * 30.0;
        out[0] = (float)(l_conf_pos + l_conf_neg + (double)pb / (double)BATCH);
        g_done_all = 0u;  // self-reset for next graph replay
    }
}

extern "C" void kernel_launch(void* const* d_in, const int* in_sizes, int n_in,
                              void* d_out, int out_size) {
    const float* pconf  = (const float*)d_in[0];
    const float* pcls   = (const float*)d_in[1];
    const float* ptxywh = (const float*)d_in[2];
    const float* gb     = (const float*)d_in[3];
    const int*   glab   = (const int*)d_in[4];
    float* out = (float*)d_out;

    yolo_loss_kernel<<<GRID_BLOCKS, THREADS>>>(pconf, pcls, ptxywh, gb, glab, out);
}